// round 4
// baseline (speedup 1.0000x reference)
#include <cuda_runtime.h>

// Problem constants
#define NPTS   8192
#define BATCH  4
#define HALF   64
#define KL     12
#define KS     6
#define BN_EPS 1e-5f
#define PTS_TOTAL (BATCH * NPTS)

// ---------------- scratch (__device__ globals; no allocation) ----------------
__device__ float g_us[PTS_TOTAL * HALF];   // A_s @ x   (point-major [pt][c])
__device__ float g_vs[PTS_TOTAL * HALF];   // B_s @ x
__device__ float g_ul[PTS_TOTAL * HALF];   // A_l @ x
__device__ float g_vl[PTS_TOTAL * HALF];   // B_l @ x
__device__ float g_maxs[BATCH * HALF * NPTS];  // [b][c][n]
__device__ float g_mins[BATCH * HALF * NPTS];
__device__ float g_maxl[BATCH * HALF * NPTS];
__device__ float g_minl[BATCH * HALF * NPTS];
__device__ int   g_idx[PTS_TOTAL * KL];        // 12 sorted NN per point (in-batch idx)
__device__ float g_st1s[128];  // [sum(64), sumsq(64)] of (u+v) for layer1 BN, short
__device__ float g_st1l[128];
__device__ float g_st2s[128];  // stats of h2 (no bias) for layer2 BN
__device__ float g_st2l[128];

// ---------------- f32x2 helpers ----------------------------------------------
__device__ __forceinline__ unsigned long long pack_dup(float a) {
    unsigned long long r;
    asm("mov.b64 %0, {%1, %1};" : "=l"(r) : "f"(a));
    return r;
}
__device__ __forceinline__ void fma2(unsigned long long& d, unsigned long long a,
                                     unsigned long long b) {
    asm("fma.rn.f32x2 %0, %1, %2, %0;" : "+l"(d) : "l"(a), "l"(b));
}
__device__ __forceinline__ void unpack2(unsigned long long p, float& lo, float& hi) {
    asm("mov.b64 {%0, %1}, %2;" : "=f"(lo), "=f"(hi) : "l"(p));
}

// ---------------- kernel 1: KNN (top-13 incl. self, emit 12) ----------------
extern __shared__ float4 sp[];  // 8192 * 16B = 128KB

__global__ void __launch_bounds__(256, 1) knn_kernel(const float* __restrict__ pos) {
    // fold stats zeroing into block 0 (kernel-boundary ordering protects readers)
    if (blockIdx.x == 0 && threadIdx.x < 128) {
        g_st1s[threadIdx.x] = 0.f; g_st1l[threadIdx.x] = 0.f;
        g_st2s[threadIdx.x] = 0.f; g_st2l[threadIdx.x] = 0.f;
    }

    const int b  = blockIdx.x >> 5;           // 32 blocks per batch
    const int q0 = (blockIdx.x & 31) << 8;    // 256 queries per block
    const float* pb = pos + b * 3 * NPTS;

    for (int j = threadIdx.x; j < NPTS; j += 256) {
        float x = pb[j], y = pb[NPTS + j], z = pb[2 * NPTS + j];
        float sq = fmaf(x, x, fmaf(y, y, z * z));
        sp[j] = make_float4(x, y, z, sq);
    }
    __syncthreads();

    const int q = q0 + threadIdx.x;
    const float4 me = sp[q];

    // Shifted metric: d2' = t.w - 2*dot  (== d2 - me.w, uniform per-query shift,
    // order-preserving). Saves one FADD in the 8192-iteration inner loop.
    float bd[KL + 1];
    int   bi[KL + 1];
#pragma unroll
    for (int m = 0; m <= KL; m++) { bd[m] = 3.4e38f; bi[m] = 0; }
    float worst = 3.4e38f;

#pragma unroll 8
    for (int j = 0; j < NPTS; j++) {
        float4 t = sp[j];
        float dot = fmaf(me.x, t.x, fmaf(me.y, t.y, me.z * t.z));
        float d2  = fmaf(-2.f, dot, t.w);
        if (d2 < worst) {   // strict < keeps earlier index on ties (stable, matches top_k)
            int m = KL;
            while (m > 0 && d2 < bd[m - 1]) { bd[m] = bd[m - 1]; bi[m] = bi[m - 1]; m--; }
            bd[m] = d2; bi[m] = j;
            worst = bd[KL];
        }
    }

    const int pt = b * NPTS + q;
#pragma unroll
    for (int m = 1; m <= KL; m++) g_idx[pt * KL + (m - 1)] = bi[m];
}

// ---------------- kernel 2: u/v feature GEMMs (64x64 x 32768 pts, x4) -------
// m = blockIdx.x & 3 : 0 -> A_s, 1 -> B_s, 2 -> A_l, 3 -> B_l
__global__ void __launch_bounds__(256) feat_kernel(const float* __restrict__ x,
                                                   const float* __restrict__ Ws1,
                                                   const float* __restrict__ Wl1) {
    __shared__ float sx[64][64];    // x[cin][n_local]
    __shared__ float sw[64][65];    // W^T [cin][cout]

    const int m    = blockIdx.x & 3;
    const int tile = blockIdx.x >> 2;           // 0..511
    const int b    = tile >> 7;
    const int n0   = (tile & 127) << 6;

    const float* W = (m < 2) ? Ws1 : Wl1;
    const bool  isA = (m & 1) == 0;
    float* out = (m == 0) ? g_us : (m == 1) ? g_vs : (m == 2) ? g_ul : g_vl;

    for (int i = threadIdx.x; i < 4096; i += 256) {
        int c = i >> 6, nl = i & 63;
        sx[c][nl] = x[(b * 64 + c) * NPTS + n0 + nl];
    }
    for (int i = threadIdx.x; i < 4096; i += 256) {
        int cin = i & 63, cout = i >> 6;
        float wb = W[cout * 128 + 64 + cin];
        sw[cin][cout] = isA ? (W[cout * 128 + cin] - wb) : wb;
    }
    __syncthreads();

    const int c    = threadIdx.x & 63;   // output channel for this thread
    const int quad = threadIdx.x >> 6;   // 16 points each
    float acc[16];
#pragma unroll
    for (int i = 0; i < 16; i++) acc[i] = 0.f;

    for (int cin = 0; cin < 64; cin++) {
        float w = sw[cin][c];
        const float4* row = (const float4*)&sx[cin][quad * 16];
#pragma unroll
        for (int i4 = 0; i4 < 4; i4++) {
            float4 xv = row[i4];
            acc[i4 * 4 + 0] = fmaf(w, xv.x, acc[i4 * 4 + 0]);
            acc[i4 * 4 + 1] = fmaf(w, xv.y, acc[i4 * 4 + 1]);
            acc[i4 * 4 + 2] = fmaf(w, xv.z, acc[i4 * 4 + 2]);
            acc[i4 * 4 + 3] = fmaf(w, xv.w, acc[i4 * 4 + 3]);
        }
    }

    const int base = b * NPTS + n0 + quad * 16;
#pragma unroll
    for (int i = 0; i < 16; i++) out[(base + i) * HALF + c] = acc[i];  // coalesced over c
}

// ---------------- kernel 3: BN1 stats over all edges (both streams fused) ----
// float4 over channel quads: thread's channel-quad (i & 15) is invariant because
// the grid stride (gridDim*256) is a multiple of 16.
__global__ void __launch_bounds__(256) stats1_kernel() {
    const int total4 = PTS_TOTAL * KL * 16;     // long edge x channel-quad tasks
    const int stride = gridDim.x * 256;
    const int tid = threadIdx.x;
    const int c0 = (tid & 15) * 4;              // this thread's channel quad

    float sl[4] = {0, 0, 0, 0}, ql[4] = {0, 0, 0, 0};
    float ss[4] = {0, 0, 0, 0}, qs[4] = {0, 0, 0, 0};

    for (int i = blockIdx.x * 256 + tid; i < total4; i += stride) {
        int e  = i >> 4;
        int pt = e / KL;
        int j  = e - pt * KL;
        int nb = g_idx[pt * KL + j];
        int b  = pt >> 13;
        int nbp = ((b << 13) + nb) * 64 + c0;
        int ptp = pt * 64 + c0;
        float4 uu = *(const float4*)&g_ul[ptp];
        float4 vv = *(const float4*)&g_vl[nbp];
        float v0 = uu.x + vv.x, v1 = uu.y + vv.y, v2 = uu.z + vv.z, v3 = uu.w + vv.w;
        sl[0] += v0; ql[0] = fmaf(v0, v0, ql[0]);
        sl[1] += v1; ql[1] = fmaf(v1, v1, ql[1]);
        sl[2] += v2; ql[2] = fmaf(v2, v2, ql[2]);
        sl[3] += v3; ql[3] = fmaf(v3, v3, ql[3]);
        if (j < KS) {
            float4 u2 = *(const float4*)&g_us[ptp];
            float4 w2 = *(const float4*)&g_vs[nbp];
            float w0 = u2.x + w2.x, w1 = u2.y + w2.y, w2z = u2.z + w2.z, w3 = u2.w + w2.w;
            ss[0] += w0; qs[0] = fmaf(w0, w0, qs[0]);
            ss[1] += w1; qs[1] = fmaf(w1, w1, qs[1]);
            ss[2] += w2z; qs[2] = fmaf(w2z, w2z, qs[2]);
            ss[3] += w3; qs[3] = fmaf(w3, w3, qs[3]);
        }
    }

    __shared__ float4 buf4[256];
    float* groups[4][4] = {{&sl[0], &sl[1], &sl[2], &sl[3]},
                           {&ql[0], &ql[1], &ql[2], &ql[3]},
                           {&ss[0], &ss[1], &ss[2], &ss[3]},
                           {&qs[0], &qs[1], &qs[2], &qs[3]}};
    float* dsts[4] = {g_st1l, g_st1l + 64, g_st1s, g_st1s + 64};
#pragma unroll
    for (int r = 0; r < 4; r++) {
        __syncthreads();
        buf4[tid] = make_float4(*groups[r][0], *groups[r][1], *groups[r][2], *groups[r][3]);
        __syncthreads();
        if (tid < 64) {
            int qd = tid >> 2, ln = tid & 3;   // channel tid = qd*4 + ln
            float tot = 0.f;
#pragma unroll
            for (int k = 0; k < 16; k++)
                tot += ((const float*)&buf4[qd + 16 * k])[ln];
            atomicAdd(&dsts[r][tid], tot);
        }
    }
}

// ---------------- kernel 4: BN1->relu->W2 GEMM->stats2 + max/min ------------
// P*K == 96 edges per block. 256 threads. f32x2 packed over edge pairs.
template <int K, int P>
__global__ void __launch_bounds__(256) edge2_kernel(bool short_stream,
                                                    const float* __restrict__ g1,
                                                    const float* __restrict__ t1,
                                                    const float* __restrict__ W2,
                                                    float cnt1) {
    const float* u  = short_stream ? g_us : g_ul;
    const float* v  = short_stream ? g_vs : g_vl;
    const float* s1 = short_stream ? g_st1s : g_st1l;
    float* st2  = short_stream ? g_st2s : g_st2l;
    float* hmax = short_stream ? g_maxs : g_maxl;
    float* hmin = short_stream ? g_mins : g_minl;

    __shared__ __align__(16) float sW[64][66];  // W2^T [cin][cout]
    __shared__ __align__(16) float sr[64][98];  // relu(bn1) TRANSPOSED: [cin][edge]
    __shared__ __align__(16) float ssc[64], ssh[64];

    const int tid = threadIdx.x;

    if (tid < 64) {
        float s = s1[tid], q = s1[64 + tid];
        float mean = s / cnt1;
        float var  = q / cnt1 - mean * mean;
        float sc   = g1[tid] * rsqrtf(var + BN_EPS);
        ssc[tid] = sc;
        ssh[tid] = fmaf(-mean, sc, t1[tid]);   // b1 cancels under BN
    }
    for (int i = tid; i < 4096; i += 256) {
        int cout = i >> 6, cin = i & 63;
        sW[cin][cout] = W2[i];                 // W2 row-major [cout][cin]
    }
    __syncthreads();

    const int pt0 = blockIdx.x * P;            // flat point over B*N

    // Phase A: build r[cin][e] in smem, float4 over channel quads.
    // task = e*16 + quad; thread's quad (tid & 15) invariant (stride 256 % 16 == 0).
    {
        const int c0 = (tid & 15) * 4;
        float4 sc4 = *(const float4*)&ssc[c0];
        float4 sh4 = *(const float4*)&ssh[c0];
#pragma unroll
        for (int it = 0; it < 6; it++) {
            int task = tid + it * 256;         // 0..1535
            int e  = task >> 4;
            int pl = e / K;
            int j  = e - pl * K;
            int pt = pt0 + pl;
            int nb = g_idx[pt * KL + j];
            int b  = pt >> 13;
            float4 uu = *(const float4*)&u[pt * 64 + c0];
            float4 vv = *(const float4*)&v[(((b << 13) + nb) << 6) + c0];
            sr[c0 + 0][e] = fmaxf(fmaf(sc4.x, uu.x + vv.x, sh4.x), 0.f);
            sr[c0 + 1][e] = fmaxf(fmaf(sc4.y, uu.y + vv.y, sh4.y), 0.f);
            sr[c0 + 2][e] = fmaxf(fmaf(sc4.z, uu.z + vv.z, sh4.z), 0.f);
            sr[c0 + 3][e] = fmaxf(fmaf(sc4.w, uu.w + vv.w, sh4.w), 0.f);
        }
    }
    __syncthreads();

    // Phase B: h2[e][cout] = sum_cin W2[cout][cin] * r[cin][e], f32x2 over edge pairs
    const int c2  = tid & 31;   // handles cout = 2*c2, 2*c2+1
    const int grp = tid >> 5;   // 8 groups x 12 edges
    const int eb  = grp * 12;

    unsigned long long acc0[6], acc1[6];
#pragma unroll
    for (int p = 0; p < 6; p++) { acc0[p] = 0ULL; acc1[p] = 0ULL; }

#pragma unroll 4
    for (int cin = 0; cin < 64; cin++) {
        float2 w = *(const float2*)&sW[cin][2 * c2];
        unsigned long long w00 = pack_dup(w.x);
        unsigned long long w11 = pack_dup(w.y);
        const unsigned long long* r2 = (const unsigned long long*)&sr[cin][eb];
#pragma unroll
        for (int p = 0; p < 6; p++) {
            unsigned long long rp = r2[p];     // broadcast across warp
            fma2(acc0[p], w00, rp);
            fma2(acc1[p], w11, rp);
        }
    }

    float a0[12], a1[12];
#pragma unroll
    for (int p = 0; p < 6; p++) {
        unpack2(acc0[p], a0[2 * p], a0[2 * p + 1]);
        unpack2(acc1[p], a1[2 * p], a1[2 * p + 1]);
    }

    // stats partials
    float ps0 = 0.f, pq0 = 0.f, ps1 = 0.f, pq1 = 0.f;
#pragma unroll
    for (int e = 0; e < 12; e++) {
        ps0 += a0[e]; pq0 = fmaf(a0[e], a0[e], pq0);
        ps1 += a1[e]; pq1 = fmaf(a1[e], a1[e], pq1);
    }

    // per-point max/min over k
    if (K == 12) {
        float m0 = a0[0], n0 = a0[0], m1 = a1[0], n1 = a1[0];
#pragma unroll
        for (int e = 1; e < 12; e++) {
            m0 = fmaxf(m0, a0[e]); n0 = fminf(n0, a0[e]);
            m1 = fmaxf(m1, a1[e]); n1 = fminf(n1, a1[e]);
        }
        int pt = pt0 + grp;
        int b = pt >> 13, n = pt & (NPTS - 1);
        hmax[(b * 64 + 2 * c2)     * NPTS + n] = m0;
        hmin[(b * 64 + 2 * c2)     * NPTS + n] = n0;
        hmax[(b * 64 + 2 * c2 + 1) * NPTS + n] = m1;
        hmin[(b * 64 + 2 * c2 + 1) * NPTS + n] = n1;
    } else {  // K == 6: two points per group
#pragma unroll
        for (int half = 0; half < 2; half++) {
            float m0 = a0[half * 6], n0 = a0[half * 6], m1 = a1[half * 6], n1 = a1[half * 6];
#pragma unroll
            for (int e = 1; e < 6; e++) {
                m0 = fmaxf(m0, a0[half * 6 + e]); n0 = fminf(n0, a0[half * 6 + e]);
                m1 = fmaxf(m1, a1[half * 6 + e]); n1 = fminf(n1, a1[half * 6 + e]);
            }
            int pt = pt0 + 2 * grp + half;
            int b = pt >> 13, n = pt & (NPTS - 1);
            hmax[(b * 64 + 2 * c2)     * NPTS + n] = m0;
            hmin[(b * 64 + 2 * c2)     * NPTS + n] = n0;
            hmax[(b * 64 + 2 * c2 + 1) * NPTS + n] = m1;
            hmin[(b * 64 + 2 * c2 + 1) * NPTS + n] = n1;
        }
    }

    // block-reduce stats2, then atomicAdd (reuse sr as buffer)
    __syncthreads();
    float* rb = &sr[0][0];
    rb[(2 * c2)     * 8 + grp] = ps0;
    rb[(2 * c2 + 1) * 8 + grp] = ps1;
    rb[1024 + (2 * c2)     * 8 + grp] = pq0;
    rb[1024 + (2 * c2 + 1) * 8 + grp] = pq1;
    __syncthreads();
    if (tid < 128) {
        int ch = tid & 63, which = tid >> 6;
        const float* src = rb + which * 1024 + ch * 8;
        float tot = src[0] + src[1] + src[2] + src[3] + src[4] + src[5] + src[6] + src[7];
        atomicAdd(&st2[which * 64 + ch], tot);
    }
}

// ---------------- kernel 5: BN2 + relu + maxpool fold + concat --------------
__global__ void __launch_bounds__(256) out_kernel(float* __restrict__ out,
                                                  const float* __restrict__ g2s,
                                                  const float* __restrict__ t2s,
                                                  const float* __restrict__ g2l,
                                                  const float* __restrict__ t2l) {
    int o = blockIdx.x * 256 + threadIdx.x;     // 4 * 128 * 8192 elements
    int n = o & (NPTS - 1);
    int c = (o >> 13) & 127;
    int b = o >> 20;
    bool lng = (c >= 64);
    int cc = c & 63;

    const float* st  = lng ? g_st2l : g_st2s;
    const float* hmx = lng ? g_maxl : g_maxs;
    const float* hmn = lng ? g_minl : g_mins;
    float cnt = lng ? (float)(PTS_TOTAL * KL) : (float)(PTS_TOTAL * KS);
    float g = lng ? g2l[cc] : g2s[cc];
    float t = lng ? t2l[cc] : t2s[cc];

    float s = st[cc], q = st[64 + cc];
    float mean = s / cnt;
    float var  = q / cnt - mean * mean;
    float sc   = g * rsqrtf(var + BN_EPS);
    float sh   = fmaf(-mean, sc, t);            // b2 cancels under BN

    int hi = (b * 64 + cc) * NPTS + n;
    float h = (sc >= 0.f) ? hmx[hi] : hmn[hi];  // relu(sc*h+sh) monotone in h
    out[o] = fmaxf(fmaf(sc, h, sh), 0.f);
}

// ---------------- launcher ---------------------------------------------------
extern "C" void kernel_launch(void* const* d_in, const int* in_sizes, int n_in,
                              void* d_out, int out_size) {
    (void)in_sizes; (void)n_in; (void)out_size;

    const float* x   = (const float*)d_in[0];
    const float* pos = (const float*)d_in[1];
    const float* Ws1 = (const float*)d_in[2];
    const float* gs1 = (const float*)d_in[4];
    const float* ts1 = (const float*)d_in[5];
    const float* Ws2 = (const float*)d_in[6];
    const float* gs2 = (const float*)d_in[8];
    const float* ts2 = (const float*)d_in[9];
    const float* Wl1 = (const float*)d_in[10];
    const float* gl1 = (const float*)d_in[12];
    const float* tl1 = (const float*)d_in[13];
    const float* Wl2 = (const float*)d_in[14];
    const float* gl2 = (const float*)d_in[16];
    const float* tl2 = (const float*)d_in[17];
    float* out = (float*)d_out;

    cudaFuncSetAttribute(knn_kernel, cudaFuncAttributeMaxDynamicSharedMemorySize, 131072);

    knn_kernel<<<BATCH * 32, 256, 131072>>>(pos);
    feat_kernel<<<2048, 256>>>(x, Ws1, Wl1);
    stats1_kernel<<<1024, 256>>>();
    edge2_kernel<KL, 8><<<PTS_TOTAL / 8, 256>>>(false, gl1, tl1, Wl2, (float)(PTS_TOTAL * KL));
    edge2_kernel<KS, 16><<<PTS_TOTAL / 16, 256>>>(true, gs1, ts1, Ws2, (float)(PTS_TOTAL * KS));
    out_kernel<<<(BATCH * 128 * NPTS) / 256, 256>>>(out, gs2, ts2, gl2, tl2);
}

// round 6
// speedup vs baseline: 1.7538x; 1.7538x over previous
#include <cuda_runtime.h>

// Problem constants
#define NPTS   8192
#define BATCH  4
#define HALF   64
#define KL     12
#define KS     6
#define BN_EPS 1e-5f
#define PTS_TOTAL (BATCH * NPTS)

// ---------------- scratch (__device__ globals; no allocation) ----------------
__device__ float g_us[PTS_TOTAL * HALF];   // A_s @ x   (point-major [pt][c])
__device__ float g_vs[PTS_TOTAL * HALF];   // B_s @ x
__device__ float g_ul[PTS_TOTAL * HALF];   // A_l @ x
__device__ float g_vl[PTS_TOTAL * HALF];   // B_l @ x
__device__ float g_maxs[BATCH * HALF * NPTS];  // [b][c][n]
__device__ float g_mins[BATCH * HALF * NPTS];
__device__ float g_maxl[BATCH * HALF * NPTS];
__device__ float g_minl[BATCH * HALF * NPTS];
__device__ int   g_idx[PTS_TOTAL * KL];        // 12 NN per point (in-batch idx)
__device__ float g_st1s[128];  // [sum(64), sumsq(64)] of (u+v) for layer1 BN, short
__device__ float g_st1l[128];
__device__ float g_st2s[128];  // stats of h2 (no bias) for layer2 BN
__device__ float g_st2l[128];

// ---------------- f32x2 helpers ----------------------------------------------
__device__ __forceinline__ unsigned long long pack_dup(float a) {
    unsigned long long r;
    asm("mov.b64 %0, {%1, %1};" : "=l"(r) : "f"(a));
    return r;
}
__device__ __forceinline__ void fma2(unsigned long long& d, unsigned long long a,
                                     unsigned long long b) {
    asm("fma.rn.f32x2 %0, %1, %2, %0;" : "+l"(d) : "l"(a), "l"(b));
}
__device__ __forceinline__ void unpack2(unsigned long long p, float& lo, float& hi) {
    asm("mov.b64 {%0, %1}, %2;" : "=f"(lo), "=f"(hi) : "l"(p));
}

// ---------------- kernel 1: KNN (top-13 incl. self, emit 12) ----------------
// Register-resident sorted list: ALL array indices are compile-time constants
// (fully unrolled carry-insertion) so bd/bi stay in registers. The previous
// dynamic-index while-loop forced the arrays to local memory (LDL/STL chains)
// which dominated runtime (~850us of the 1147us baseline).
extern __shared__ float4 sp[];  // 8192 * 16B = 128KB

__global__ void __launch_bounds__(256, 1) knn_kernel(const float* __restrict__ pos) {
    // fold stats zeroing into block 0 (kernel-boundary ordering protects readers)
    if (blockIdx.x == 0 && threadIdx.x < 128) {
        g_st1s[threadIdx.x] = 0.f; g_st1l[threadIdx.x] = 0.f;
        g_st2s[threadIdx.x] = 0.f; g_st2l[threadIdx.x] = 0.f;
    }

    const int b  = blockIdx.x >> 5;           // 32 blocks per batch
    const int q0 = (blockIdx.x & 31) << 8;    // 256 queries per block
    const float* pb = pos + b * 3 * NPTS;

    for (int j = threadIdx.x; j < NPTS; j += 256) {
        float x = pb[j], y = pb[NPTS + j], z = pb[2 * NPTS + j];
        float sq = fmaf(x, x, fmaf(y, y, z * z));
        sp[j] = make_float4(x, y, z, sq);
    }
    __syncthreads();

    const int q = q0 + threadIdx.x;
    const float4 me = sp[q];

    // Shifted metric: d2' = t.w - 2*dot (== d2 - me.w, order-preserving per query).
    // Self is the strict minimum: d2'(q,q) = -me.w; always lands in slot 0.
    float bd[KL + 1];
    int   bi[KL + 1];
#pragma unroll
    for (int m = 0; m <= KL; m++) { bd[m] = 3.4e38f; bi[m] = 0; }
    float worst = 3.4e38f;

#pragma unroll 4
    for (int j = 0; j < NPTS; j++) {
        float4 t = sp[j];
        float dot = fmaf(me.x, t.x, fmaf(me.y, t.y, me.z * t.z));
        float d2  = fmaf(-2.f, dot, t.w);
        if (d2 < worst) {   // strict < keeps earlier index on ties (stable, matches top_k)
            float cd = d2; int ci = j;
#pragma unroll
            for (int m = 0; m <= KL; m++) {   // carry-insertion, constant indices only
                bool ins = cd < bd[m];
                float od = bd[m]; int oi = bi[m];
                bd[m] = ins ? cd : od;
                bi[m] = ins ? ci : oi;
                cd = ins ? od : cd;
                ci = ins ? oi : ci;
            }
            worst = bd[KL];
        }
    }

    const int pt = b * NPTS + q;
#pragma unroll
    for (int m = 1; m <= KL; m++) g_idx[pt * KL + (m - 1)] = bi[m];
}

// ---------------- kernel 2: u/v feature GEMMs (64x64 x 32768 pts, x4) -------
// m = blockIdx.x & 3 : 0 -> A_s, 1 -> B_s, 2 -> A_l, 3 -> B_l
__global__ void __launch_bounds__(256) feat_kernel(const float* __restrict__ x,
                                                   const float* __restrict__ Ws1,
                                                   const float* __restrict__ Wl1) {
    __shared__ float sx[64][64];    // x[cin][n_local]
    __shared__ float sw[64][65];    // W^T [cin][cout]

    const int m    = blockIdx.x & 3;
    const int tile = blockIdx.x >> 2;           // 0..511
    const int b    = tile >> 7;
    const int n0   = (tile & 127) << 6;

    const float* W = (m < 2) ? Ws1 : Wl1;
    const bool  isA = (m & 1) == 0;
    float* out = (m == 0) ? g_us : (m == 1) ? g_vs : (m == 2) ? g_ul : g_vl;

    for (int i = threadIdx.x; i < 4096; i += 256) {
        int c = i >> 6, nl = i & 63;
        sx[c][nl] = x[(b * 64 + c) * NPTS + n0 + nl];
    }
    for (int i = threadIdx.x; i < 4096; i += 256) {
        int cin = i & 63, cout = i >> 6;
        float wb = W[cout * 128 + 64 + cin];
        sw[cin][cout] = isA ? (W[cout * 128 + cin] - wb) : wb;
    }
    __syncthreads();

    const int c    = threadIdx.x & 63;   // output channel for this thread
    const int quad = threadIdx.x >> 6;   // 16 points each
    float acc[16];
#pragma unroll
    for (int i = 0; i < 16; i++) acc[i] = 0.f;

    for (int cin = 0; cin < 64; cin++) {
        float w = sw[cin][c];
        const float4* row = (const float4*)&sx[cin][quad * 16];
#pragma unroll
        for (int i4 = 0; i4 < 4; i4++) {
            float4 xv = row[i4];
            acc[i4 * 4 + 0] = fmaf(w, xv.x, acc[i4 * 4 + 0]);
            acc[i4 * 4 + 1] = fmaf(w, xv.y, acc[i4 * 4 + 1]);
            acc[i4 * 4 + 2] = fmaf(w, xv.z, acc[i4 * 4 + 2]);
            acc[i4 * 4 + 3] = fmaf(w, xv.w, acc[i4 * 4 + 3]);
        }
    }

    const int base = b * NPTS + n0 + quad * 16;
#pragma unroll
    for (int i = 0; i < 16; i++) out[(base + i) * HALF + c] = acc[i];  // coalesced over c
}

// ---------------- kernel 3: BN1 stats over all edges (both streams fused) ----
// float4 over channel quads: thread's channel-quad (i & 15) is invariant because
// the grid stride (gridDim*256) is a multiple of 16.
__global__ void __launch_bounds__(256) stats1_kernel() {
    const int total4 = PTS_TOTAL * KL * 16;     // long edge x channel-quad tasks
    const int stride = gridDim.x * 256;
    const int tid = threadIdx.x;
    const int c0 = (tid & 15) * 4;              // this thread's channel quad

    float sl[4] = {0, 0, 0, 0}, ql[4] = {0, 0, 0, 0};
    float ss[4] = {0, 0, 0, 0}, qs[4] = {0, 0, 0, 0};

    for (int i = blockIdx.x * 256 + tid; i < total4; i += stride) {
        int e  = i >> 4;
        int pt = e / KL;
        int j  = e - pt * KL;
        int nb = g_idx[pt * KL + j];
        int b  = pt >> 13;
        int nbp = ((b << 13) + nb) * 64 + c0;
        int ptp = pt * 64 + c0;
        float4 uu = *(const float4*)&g_ul[ptp];
        float4 vv = *(const float4*)&g_vl[nbp];
        float v0 = uu.x + vv.x, v1 = uu.y + vv.y, v2 = uu.z + vv.z, v3 = uu.w + vv.w;
        sl[0] += v0; ql[0] = fmaf(v0, v0, ql[0]);
        sl[1] += v1; ql[1] = fmaf(v1, v1, ql[1]);
        sl[2] += v2; ql[2] = fmaf(v2, v2, ql[2]);
        sl[3] += v3; ql[3] = fmaf(v3, v3, ql[3]);
        if (j < KS) {
            float4 u2 = *(const float4*)&g_us[ptp];
            float4 w2 = *(const float4*)&g_vs[nbp];
            float w0 = u2.x + w2.x, w1 = u2.y + w2.y, w2z = u2.z + w2.z, w3 = u2.w + w2.w;
            ss[0] += w0; qs[0] = fmaf(w0, w0, qs[0]);
            ss[1] += w1; qs[1] = fmaf(w1, w1, qs[1]);
            ss[2] += w2z; qs[2] = fmaf(w2z, w2z, qs[2]);
            ss[3] += w3; qs[3] = fmaf(w3, w3, qs[3]);
        }
    }

    __shared__ float4 buf4[256];
    float* groups[4][4] = {{&sl[0], &sl[1], &sl[2], &sl[3]},
                           {&ql[0], &ql[1], &ql[2], &ql[3]},
                           {&ss[0], &ss[1], &ss[2], &ss[3]},
                           {&qs[0], &qs[1], &qs[2], &qs[3]}};
    float* dsts[4] = {g_st1l, g_st1l + 64, g_st1s, g_st1s + 64};
#pragma unroll
    for (int r = 0; r < 4; r++) {
        __syncthreads();
        buf4[tid] = make_float4(*groups[r][0], *groups[r][1], *groups[r][2], *groups[r][3]);
        __syncthreads();
        if (tid < 64) {
            int qd = tid >> 2, ln = tid & 3;   // channel tid = qd*4 + ln
            float tot = 0.f;
#pragma unroll
            for (int k = 0; k < 16; k++)
                tot += ((const float*)&buf4[qd + 16 * k])[ln];
            atomicAdd(&dsts[r][tid], tot);
        }
    }
}

// ---------------- kernel 4: BN1->relu->W2 GEMM->stats2 + max/min ------------
// P*K == 96 edges per block. 256 threads. f32x2 packed over edge pairs.
template <int K, int P>
__global__ void __launch_bounds__(256) edge2_kernel(bool short_stream,
                                                    const float* __restrict__ g1,
                                                    const float* __restrict__ t1,
                                                    const float* __restrict__ W2,
                                                    float cnt1) {
    const float* u  = short_stream ? g_us : g_ul;
    const float* v  = short_stream ? g_vs : g_vl;
    const float* s1 = short_stream ? g_st1s : g_st1l;
    float* st2  = short_stream ? g_st2s : g_st2l;
    float* hmax = short_stream ? g_maxs : g_maxl;
    float* hmin = short_stream ? g_mins : g_minl;

    __shared__ __align__(16) float sW[64][66];  // W2^T [cin][cout]
    __shared__ __align__(16) float sr[64][98];  // relu(bn1) TRANSPOSED: [cin][edge]
    __shared__ __align__(16) float ssc[64], ssh[64];

    const int tid = threadIdx.x;

    if (tid < 64) {
        float s = s1[tid], q = s1[64 + tid];
        float mean = s / cnt1;
        float var  = q / cnt1 - mean * mean;
        float sc   = g1[tid] * rsqrtf(var + BN_EPS);
        ssc[tid] = sc;
        ssh[tid] = fmaf(-mean, sc, t1[tid]);   // b1 cancels under BN
    }
    for (int i = tid; i < 4096; i += 256) {
        int cout = i >> 6, cin = i & 63;
        sW[cin][cout] = W2[i];                 // W2 row-major [cout][cin]
    }
    __syncthreads();

    const int pt0 = blockIdx.x * P;            // flat point over B*N

    // Phase A: build r[cin][e] in smem, float4 over channel quads.
    // task = e*16 + quad; thread's quad (tid & 15) invariant (stride 256 % 16 == 0).
    {
        const int c0 = (tid & 15) * 4;
        float4 sc4 = *(const float4*)&ssc[c0];
        float4 sh4 = *(const float4*)&ssh[c0];
#pragma unroll
        for (int it = 0; it < 6; it++) {
            int task = tid + it * 256;         // 0..1535
            int e  = task >> 4;
            int pl = e / K;
            int j  = e - pl * K;
            int pt = pt0 + pl;
            int nb = g_idx[pt * KL + j];
            int b  = pt >> 13;
            float4 uu = *(const float4*)&u[pt * 64 + c0];
            float4 vv = *(const float4*)&v[(((b << 13) + nb) << 6) + c0];
            sr[c0 + 0][e] = fmaxf(fmaf(sc4.x, uu.x + vv.x, sh4.x), 0.f);
            sr[c0 + 1][e] = fmaxf(fmaf(sc4.y, uu.y + vv.y, sh4.y), 0.f);
            sr[c0 + 2][e] = fmaxf(fmaf(sc4.z, uu.z + vv.z, sh4.z), 0.f);
            sr[c0 + 3][e] = fmaxf(fmaf(sc4.w, uu.w + vv.w, sh4.w), 0.f);
        }
    }
    __syncthreads();

    // Phase B: h2[e][cout] = sum_cin W2[cout][cin] * r[cin][e], f32x2 over edge pairs
    const int c2  = tid & 31;   // handles cout = 2*c2, 2*c2+1
    const int grp = tid >> 5;   // 8 groups x 12 edges
    const int eb  = grp * 12;

    unsigned long long acc0[6], acc1[6];
#pragma unroll
    for (int p = 0; p < 6; p++) { acc0[p] = 0ULL; acc1[p] = 0ULL; }

#pragma unroll 4
    for (int cin = 0; cin < 64; cin++) {
        float2 w = *(const float2*)&sW[cin][2 * c2];
        unsigned long long w00 = pack_dup(w.x);
        unsigned long long w11 = pack_dup(w.y);
        const unsigned long long* r2 = (const unsigned long long*)&sr[cin][eb];
#pragma unroll
        for (int p = 0; p < 6; p++) {
            unsigned long long rp = r2[p];     // broadcast across warp
            fma2(acc0[p], w00, rp);
            fma2(acc1[p], w11, rp);
        }
    }

    float a0[12], a1[12];
#pragma unroll
    for (int p = 0; p < 6; p++) {
        unpack2(acc0[p], a0[2 * p], a0[2 * p + 1]);
        unpack2(acc1[p], a1[2 * p], a1[2 * p + 1]);
    }

    // stats partials
    float ps0 = 0.f, pq0 = 0.f, ps1 = 0.f, pq1 = 0.f;
#pragma unroll
    for (int e = 0; e < 12; e++) {
        ps0 += a0[e]; pq0 = fmaf(a0[e], a0[e], pq0);
        ps1 += a1[e]; pq1 = fmaf(a1[e], a1[e], pq1);
    }

    // per-point max/min over k
    if (K == 12) {
        float m0 = a0[0], n0 = a0[0], m1 = a1[0], n1 = a1[0];
#pragma unroll
        for (int e = 1; e < 12; e++) {
            m0 = fmaxf(m0, a0[e]); n0 = fminf(n0, a0[e]);
            m1 = fmaxf(m1, a1[e]); n1 = fminf(n1, a1[e]);
        }
        int pt = pt0 + grp;
        int b = pt >> 13, n = pt & (NPTS - 1);
        hmax[(b * 64 + 2 * c2)     * NPTS + n] = m0;
        hmin[(b * 64 + 2 * c2)     * NPTS + n] = n0;
        hmax[(b * 64 + 2 * c2 + 1) * NPTS + n] = m1;
        hmin[(b * 64 + 2 * c2 + 1) * NPTS + n] = n1;
    } else {  // K == 6: two points per group
#pragma unroll
        for (int half = 0; half < 2; half++) {
            float m0 = a0[half * 6], n0 = a0[half * 6], m1 = a1[half * 6], n1 = a1[half * 6];
#pragma unroll
            for (int e = 1; e < 6; e++) {
                m0 = fmaxf(m0, a0[half * 6 + e]); n0 = fminf(n0, a0[half * 6 + e]);
                m1 = fmaxf(m1, a1[half * 6 + e]); n1 = fminf(n1, a1[half * 6 + e]);
            }
            int pt = pt0 + 2 * grp + half;
            int b = pt >> 13, n = pt & (NPTS - 1);
            hmax[(b * 64 + 2 * c2)     * NPTS + n] = m0;
            hmin[(b * 64 + 2 * c2)     * NPTS + n] = n0;
            hmax[(b * 64 + 2 * c2 + 1) * NPTS + n] = m1;
            hmin[(b * 64 + 2 * c2 + 1) * NPTS + n] = n1;
        }
    }

    // block-reduce stats2, then atomicAdd (reuse sr as buffer)
    __syncthreads();
    float* rb = &sr[0][0];
    rb[(2 * c2)     * 8 + grp] = ps0;
    rb[(2 * c2 + 1) * 8 + grp] = ps1;
    rb[1024 + (2 * c2)     * 8 + grp] = pq0;
    rb[1024 + (2 * c2 + 1) * 8 + grp] = pq1;
    __syncthreads();
    if (tid < 128) {
        int ch = tid & 63, which = tid >> 6;
        const float* src = rb + which * 1024 + ch * 8;
        float tot = src[0] + src[1] + src[2] + src[3] + src[4] + src[5] + src[6] + src[7];
        atomicAdd(&st2[which * 64 + ch], tot);
    }
}

// ---------------- kernel 5: BN2 + relu + maxpool fold + concat --------------
__global__ void __launch_bounds__(256) out_kernel(float* __restrict__ out,
                                                  const float* __restrict__ g2s,
                                                  const float* __restrict__ t2s,
                                                  const float* __restrict__ g2l,
                                                  const float* __restrict__ t2l) {
    int o = blockIdx.x * 256 + threadIdx.x;     // 4 * 128 * 8192 elements
    int n = o & (NPTS - 1);
    int c = (o >> 13) & 127;
    int b = o >> 20;
    bool lng = (c >= 64);
    int cc = c & 63;

    const float* st  = lng ? g_st2l : g_st2s;
    const float* hmx = lng ? g_maxl : g_maxs;
    const float* hmn = lng ? g_minl : g_mins;
    float cnt = lng ? (float)(PTS_TOTAL * KL) : (float)(PTS_TOTAL * KS);
    float g = lng ? g2l[cc] : g2s[cc];
    float t = lng ? t2l[cc] : t2s[cc];

    float s = st[cc], q = st[64 + cc];
    float mean = s / cnt;
    float var  = q / cnt - mean * mean;
    float sc   = g * rsqrtf(var + BN_EPS);
    float sh   = fmaf(-mean, sc, t);            // b2 cancels under BN

    int hi = (b * 64 + cc) * NPTS + n;
    float h = (sc >= 0.f) ? hmx[hi] : hmn[hi];  // relu(sc*h+sh) monotone in h
    out[o] = fmaxf(fmaf(sc, h, sh), 0.f);
}

// ---------------- launcher ---------------------------------------------------
extern "C" void kernel_launch(void* const* d_in, const int* in_sizes, int n_in,
                              void* d_out, int out_size) {
    (void)in_sizes; (void)n_in; (void)out_size;

    const float* x   = (const float*)d_in[0];
    const float* pos = (const float*)d_in[1];
    const float* Ws1 = (const float*)d_in[2];
    const float* gs1 = (const float*)d_in[4];
    const float* ts1 = (const float*)d_in[5];
    const float* Ws2 = (const float*)d_in[6];
    const float* gs2 = (const float*)d_in[8];
    const float* ts2 = (const float*)d_in[9];
    const float* Wl1 = (const float*)d_in[10];
    const float* gl1 = (const float*)d_in[12];
    const float* tl1 = (const float*)d_in[13];
    const float* Wl2 = (const float*)d_in[14];
    const float* gl2 = (const float*)d_in[16];
    const float* tl2 = (const float*)d_in[17];
    float* out = (float*)d_out;

    cudaFuncSetAttribute(knn_kernel, cudaFuncAttributeMaxDynamicSharedMemorySize, 131072);

    knn_kernel<<<BATCH * 32, 256, 131072>>>(pos);
    feat_kernel<<<2048, 256>>>(x, Ws1, Wl1);
    stats1_kernel<<<1024, 256>>>();
    edge2_kernel<KL, 8><<<PTS_TOTAL / 8, 256>>>(false, gl1, tl1, Wl2, (float)(PTS_TOTAL * KL));
    edge2_kernel<KS, 16><<<PTS_TOTAL / 16, 256>>>(true, gs1, ts1, Ws2, (float)(PTS_TOTAL * KS));
    out_kernel<<<(BATCH * 128 * NPTS) / 256, 256>>>(out, gs2, ts2, gl2, tl2);
}